// round 5
// baseline (speedup 1.0000x reference)
#include <cuda_runtime.h>
#include <math.h>

// ---------------- problem constants ----------------
#define IN_CH   512
#define OUT_CH  512
#define KK      9
#define STYLE_DIM 512
#define B_SZ    8
#define HW      64
#define NPIX    4096              // 64*64
#define CONV_SCALE (1.0f / 67.8822509939086f)   // 1/sqrt(512*9) = 1/sqrt(4608)
#define MOD_SCALE  (1.0f / 22.627416997969522f) // 1/sqrt(512)
#define EPSV 1e-8f

// ---------------- device scratch (no allocs allowed) ----------------
__device__ float g_w5[IN_CH * KK * OUT_CH];   // layout [i][t][o]  (o contiguous)
__device__ float g_W2t[IN_CH * OUT_CH];       // layout [i][o]     (o contiguous)
__device__ float g_sc[B_SZ * IN_CH];          // CONV_SCALE * s[b,i]
__device__ float g_demod[B_SZ * OUT_CH];

// ---------------- f32x2 helpers (sm_103a packed fp32) ----------------
__device__ __forceinline__ unsigned long long pk2(float a, float b) {
    unsigned long long r;
    asm("mov.b64 %0, {%1,%2};" : "=l"(r) : "f"(a), "f"(b));
    return r;
}
__device__ __forceinline__ void unpk2(unsigned long long v, float& lo, float& hi) {
    asm("mov.b64 {%0,%1}, %2;" : "=f"(lo), "=f"(hi) : "l"(v));
}
__device__ __forceinline__ void fma2(unsigned long long& d, unsigned long long a,
                                     unsigned long long b) {
    asm("fma.rn.f32x2 %0, %1, %2, %0;" : "+l"(d) : "l"(a), "l"(b));
}

// ======================================================================
// Kernel 1: w5[o,i,t] = weight + relu(A @ relu(B @ B_inst)); also W2[o,i]
// grid 512 (one block per o), 256 threads
// ======================================================================
__global__ __launch_bounds__(256) void prep_w5_kernel(
    const float* __restrict__ weight,     // [1,512,512,3,3]
    const float* __restrict__ llB,        // [512,4]
    const float* __restrict__ llBinst,    // [4,4,9]
    const float* __restrict__ llA)        // [512,4]
{
    const int o = blockIdx.x;
    const int tid = threadIdx.x;
    __shared__ float Bo[4];
    __shared__ float Bm[4][9];   // relu(sum_r llB[o,r]*llBinst[b_,r,t])

    if (tid < 4) Bo[tid] = llB[o * 4 + tid];
    __syncthreads();
    if (tid < 36) {
        int b_ = tid / 9, t = tid - b_ * 9;
        float acc = 0.f;
#pragma unroll
        for (int r = 0; r < 4; r++) acc += Bo[r] * llBinst[(b_ * 4 + r) * 9 + t];
        Bm[b_][t] = fmaxf(acc, 0.f);
    }
    __syncthreads();

    for (int i = tid; i < IN_CH; i += 256) {
        float A0 = llA[i * 4 + 0], A1 = llA[i * 4 + 1];
        float A2 = llA[i * 4 + 2], A3 = llA[i * 4 + 3];
        float w2sum = 0.f;
#pragma unroll
        for (int t = 0; t < 9; t++) {
            float add = fmaxf(A0 * Bm[0][t] + A1 * Bm[1][t] + A2 * Bm[2][t] + A3 * Bm[3][t], 0.f);
            float w = weight[(o * IN_CH + i) * 9 + t] + add;   // LORA_ALPHA_CONV = 1
            g_w5[(i * 9 + t) * OUT_CH + o] = w;
            w2sum += w * w;
        }
        g_W2t[i * OUT_CH + o] = w2sum;
    }
}

// ======================================================================
// Kernel 2: sc[b,i] = CONV_SCALE * (MOD_SCALE * style @ w_fc.T + b_fc)
//           w_fc = mod_weight + fc_lora_B @ fc_lora_A.T
// grid 8 (per batch), 512 threads: one warp per i, lanes reduce over j
// ======================================================================
__global__ __launch_bounds__(512) void prep_s_kernel(
    const float* __restrict__ style,    // [8,512]
    const float* __restrict__ modW,     // [512,512]
    const float* __restrict__ modB,     // [512]
    const float* __restrict__ fcA,      // [512,4]
    const float* __restrict__ fcB,      // [512,4]
    const float* __restrict__ fcBias)   // [512]
{
    const int b = blockIdx.x;
    const int tid = threadIdx.x;
    __shared__ float sty[STYLE_DIM];
    sty[tid] = style[b * STYLE_DIM + tid];
    __syncthreads();

    const int warp = tid >> 5, lane = tid & 31;
    for (int i = warp; i < IN_CH; i += 16) {
        float4 fb = *(const float4*)&fcB[i * 4];
        float acc = 0.f;
        for (int j = lane; j < STYLE_DIM; j += 32) {
            float4 fa = *(const float4*)&fcA[j * 4];
            float wfc = modW[i * STYLE_DIM + j] +
                        (fb.x * fa.x + fb.y * fa.y + fb.z * fa.z + fb.w * fa.w);
            acc += sty[j] * wfc;
        }
#pragma unroll
        for (int off = 16; off; off >>= 1) acc += __shfl_xor_sync(0xFFFFFFFFu, acc, off);
        if (lane == 0) {
            float s = acc * MOD_SCALE + modB[i] + fcBias[i];
            g_sc[b * IN_CH + i] = s * CONV_SCALE;
        }
    }
}

// ======================================================================
// Kernel 3: demod[b,o] = rsqrt(sum_i sc[b,i]^2 * W2[o,i] + eps)
// 4096 threads total
// ======================================================================
__global__ __launch_bounds__(256) void prep_demod_kernel()
{
    const int id = blockIdx.x * 256 + threadIdx.x;
    const int b = id >> 9, o = id & 511;
    const float* scp = &g_sc[b * IN_CH];
    float acc = 0.f;
#pragma unroll 4
    for (int i = 0; i < IN_CH; i++) {
        float sv = scp[i];
        acc = fmaf(sv * sv, g_W2t[i * OUT_CH + o], acc);
    }
    g_demod[b * OUT_CH + o] = rsqrtf(acc + EPSV);
}

// ======================================================================
// Kernel 4: main conv.
//   out[b,o,y,x] = demod[b,o] * sum_{i,t} w5[o,i,t] * sc[b,i] * in[b,i,y+kh-1,x+kw-1]
// Block: (b, 64 o-channels, 2 output rows of width 64) = 64o x 128px
// 256 threads: ty=tid/16 -> o = o0+ty*4..+3 ; tx=tid%16 -> x = tx + u*16
// Accumulators packed f32x2 over pixel pairs (u0,u1),(u2,u3).
// ======================================================================
#define ICB 8
__global__ __launch_bounds__(256) void conv_kernel(
    const float* __restrict__ input,   // [8,512,64,64]
    float* __restrict__ out)           // [8,512,64,64]
{
    const int b  = blockIdx.z;
    const int o0 = blockIdx.y << 6;
    const int y0 = blockIdx.x << 1;
    const int tid = threadIdx.x;
    const int tx = tid & 15;
    const int ty = tid >> 4;

    __shared__ float sIn[ICB][4][66];     // rows y0-1..y0+2, cols x=-1..64 (+1 offset)
    __shared__ float sW[ICB][9][64];      // [ic][tap][o-o0]

    unsigned long long acc[4][2][2];
#pragma unroll
    for (int a = 0; a < 4; a++)
#pragma unroll
        for (int r = 0; r < 2; r++) { acc[a][r][0] = 0ull; acc[a][r][1] = 0ull; }

    const float* inB = input + (size_t)b * IN_CH * NPIX;
    const float* scB = &g_sc[b * IN_CH];

#pragma unroll 1
    for (int ic0 = 0; ic0 < IN_CH; ic0 += ICB) {
        __syncthreads();
        // ---- load scaled input tile: ICB*4*66 = 2112 floats ----
#pragma unroll
        for (int l = 0; l < 9; l++) {
            int idx = tid + l * 256;
            if (idx < ICB * 4 * 66) {
                int ic  = idx / 264;
                int rem = idx - ic * 264;
                int row = rem / 66;
                int col = rem - row * 66;
                int y = y0 - 1 + row;
                int x = col - 1;
                float v = 0.f;
                if ((unsigned)y < 64u && (unsigned)x < 64u)
                    v = inB[(ic0 + ic) * NPIX + y * 64 + x] * scB[ic0 + ic];
                sIn[ic][row][col] = v;
            }
        }
        // ---- load weight tile: ICB*9*64 = 4608 floats (coalesced over o) ----
#pragma unroll
        for (int l = 0; l < 18; l++) {
            int idx = tid + l * 256;
            int ic  = idx / 576;
            int rem = idx - ic * 576;
            sW[ic][rem >> 6][rem & 63] =
                g_w5[(ic0 + ic) * (9 * OUT_CH) + (rem >> 6) * OUT_CH + o0 + (rem & 63)];
        }
        __syncthreads();

        // ---- compute ----
#pragma unroll 2
        for (int ic = 0; ic < ICB; ic++) {
#pragma unroll
            for (int t = 0; t < 9; t++) {
                const int kh = t / 3;
                const int kw = t - kh * 3;
                float4 w4 = *(const float4*)&sW[ic][t][ty << 2];
                unsigned long long w0 = pk2(w4.x, w4.x);
                unsigned long long w1 = pk2(w4.y, w4.y);
                unsigned long long w2 = pk2(w4.z, w4.z);
                unsigned long long w3 = pk2(w4.w, w4.w);
#pragma unroll
                for (int r = 0; r < 2; r++) {
                    const float* rp = &sIn[ic][r + kh][tx + kw];
                    float a0 = rp[0], a1 = rp[16], a2 = rp[32], a3 = rp[48];
                    unsigned long long p01 = pk2(a0, a1);
                    unsigned long long p23 = pk2(a2, a3);
                    fma2(acc[0][r][0], w0, p01);  fma2(acc[0][r][1], w0, p23);
                    fma2(acc[1][r][0], w1, p01);  fma2(acc[1][r][1], w1, p23);
                    fma2(acc[2][r][0], w2, p01);  fma2(acc[2][r][1], w2, p23);
                    fma2(acc[3][r][0], w3, p01);  fma2(acc[3][r][1], w3, p23);
                }
            }
        }
    }

    // ---- epilogue: apply demod, store ----
#pragma unroll
    for (int uo = 0; uo < 4; uo++) {
        const int o = o0 + (ty << 2) + uo;
        const float dm = g_demod[b * OUT_CH + o];
#pragma unroll
        for (int r = 0; r < 2; r++) {
            float* op = out + (((size_t)b * OUT_CH + o) * 64 + (y0 + r)) * 64 + tx;
#pragma unroll
            for (int p = 0; p < 2; p++) {
                float lo, hi;
                unpk2(acc[uo][r][p], lo, hi);
                op[(2 * p) * 16]     = lo * dm;
                op[(2 * p + 1) * 16] = hi * dm;
            }
        }
    }
}

// ======================================================================
extern "C" void kernel_launch(void* const* d_in, const int* in_sizes, int n_in,
                              void* d_out, int out_size)
{
    const float* input   = (const float*)d_in[0];
    const float* style   = (const float*)d_in[1];
    const float* weight  = (const float*)d_in[2];
    const float* llB     = (const float*)d_in[3];
    const float* llBinst = (const float*)d_in[4];
    const float* llA     = (const float*)d_in[5];
    const float* modW    = (const float*)d_in[6];
    const float* modB    = (const float*)d_in[7];
    const float* fcA     = (const float*)d_in[8];
    const float* fcB     = (const float*)d_in[9];
    const float* fcBias  = (const float*)d_in[10];
    float* out = (float*)d_out;

    prep_w5_kernel<<<512, 256>>>(weight, llB, llBinst, llA);
    prep_s_kernel<<<8, 512>>>(style, modW, modB, fcA, fcB, fcBias);
    prep_demod_kernel<<<16, 256>>>();
    conv_kernel<<<dim3(32, 8, 8), 256>>>(input, out);
}